// round 15
// baseline (speedup 1.0000x reference)
#include <cuda_runtime.h>
#include <stdint.h>

// Problem constants
#define NSAMP 1000000
#define KMIX  64
#define DDIM  16

// Opaque 1 — global load ptxas cannot constant-fold; mad.lo.u32 by this value
// stays IMAD (off the saturated ALU pipe).
__device__ uint32_t g_one = 1u;

// ---------------------------------------------------------------------------
// Threefry-2x32, key (0,42), partitionable counter (0,i), combine o0^o1.
// Input c42 = i + 42 (prefolded). Round adds and keyschedule adds are forced
// IMADs (off-ALU); rotate+xor (SHF+LOP3) are the irreducible ALU floor.
// ---------------------------------------------------------------------------
__device__ __forceinline__ uint32_t tf_bits(uint32_t c42, uint32_t one) {
    uint32_t x1 = c42;
    uint32_t x0 = x1;                       // round-1 specialized (x0 starts 0)
    x1 = __funnelshift_l(x1, x1, 13) ^ x0;

#define TFR(r) { asm("mad.lo.u32 %0, %1, %2, %0;" : "+r"(x0) : "r"(x1), "r"(one)); \
                 x1 = __funnelshift_l(x1, x1, (r)) ^ x0; }
#define KADD(v, c) asm("mad.lo.u32 %0, %1, %2, %0;" : "+r"(v) : "r"(one), "n"(c))
    TFR(15) TFR(26) TFR(6)
    KADD(x0, 42);          KADD(x1, 0x1BD11BF1);   // ks2+1
    TFR(17) TFR(29) TFR(16) TFR(24)
    KADD(x0, 0x1BD11BF0);  KADD(x1, 2);            // ks2 ; ks0+2
    TFR(13) TFR(15) TFR(26) TFR(6)
    /* x0 += ks0 (=0): skip */ KADD(x1, 45);       // ks1+3
    TFR(17) TFR(29) TFR(16) TFR(24)
    KADD(x0, 42);          KADD(x1, 0x1BD11BF4);   // ks1 ; ks2+4
    TFR(13) TFR(15) TFR(26) TFR(6)
    KADD(x0, 0x1BD11BF0);  KADD(x1, 5);            // ks2 ; ks0+5
#undef TFR
#undef KADD
    return x0 ^ x1;
}

// ---------------------------------------------------------------------------
// Fused kernel, 2 samples/thread k-interleaved (one w2[k] LDS serves both;
// loop overhead halved), then warp-cooperative matvec (8 passes, 4 lanes per
// sample, z via shfl). Screen: argmin_k log2(u_k)*(-ln2/p_k); exact
// reference-formula rescan when top-2 margin < 4e-4 + 4e-4*m1 (3.3x the
// worst-case MUFU.LG2-induced margin error of 1.2e-4).
// ---------------------------------------------------------------------------
__global__ __launch_bounds__(256) void fused_kernel(
    const float* __restrict__ pi,
    const float* __restrict__ x,
    const float* __restrict__ means,
    const float* __restrict__ Ls,
    float* __restrict__ y)
{
    __shared__ float s_w2n[KMIX];
    __shared__ float s_logit[KMIX];
    __shared__ float s_sum;

    // Block-local logits (serial sum order identical to verified runs).
    if (threadIdx.x == 0) {
        float s = 0.0f;
        for (int k = 0; k < KMIX; k++) s += pi[k];
        s_sum = s;
    }
    __syncthreads();
    if (threadIdx.x < KMIX) {
        float ssum = s_sum;
        s_logit[threadIdx.x] = logf(pi[threadIdx.x] / ssum);
        s_w2n[threadIdx.x]   = -0.6931471805599453f * (ssum / pi[threadIdx.x]);
    }
    __syncthreads();

    int lane   = threadIdx.x & 31;
    int warpId = threadIdx.x >> 5;
    unsigned warpBase = blockIdx.x * 512u + (unsigned)warpId * 64u;  // 64 samples/warp
    if (warpBase >= NSAMP) return;          // whole-warp guard (NSAMP % 64 == 0)

    unsigned n0 = warpBase + (unsigned)lane;        // this thread's samples
    unsigned n1 = n0 + 32u;

    uint32_t one = g_one;                   // opaque 1 (global load)
    uint32_t b42_0 = n0 * 64u + 42u;
    uint32_t b42_1 = n1 * 64u + 42u;

    // ---- categorical sampling: k outer, 2 samples inner ----
    const float INF = __int_as_float(0x7F800000);
    float m1a = INF, m2a = INF, m1b = INF, m2b = INF;
    int i1a = 0, i1b = 0;

    #pragma unroll 4
    for (int k = 0; k < KMIX; k++) {
        float w2 = s_w2n[k];                // one LDS for 2 elements
        uint32_t ck0, ck1;
        asm("mad.lo.u32 %0, %1, %2, %3;" : "=r"(ck0) : "r"((uint32_t)k), "r"(one), "r"(b42_0));
        asm("mad.lo.u32 %0, %1, %2, %3;" : "=r"(ck1) : "r"((uint32_t)k), "r"(one), "r"(b42_1));
        {
            uint32_t bits = tf_bits(ck0, one);
            uint32_t fb;
            asm("mad.hi.u32 %0, %1, %2, %3;"
                : "=r"(fb) : "r"(bits), "r"(0x00800000u), "r"(0x3F800000u));
            float u = __uint_as_float(fb) - 1.0f;       // [0,1)
            float m = __log2f(u) * w2;                  // >=0 (u=0 -> +inf)
            if (m < m1a) { m2a = m1a; m1a = m; i1a = k; }
            else         { m2a = fminf(m2a, m); }
        }
        {
            uint32_t bits = tf_bits(ck1, one);
            uint32_t fb;
            asm("mad.hi.u32 %0, %1, %2, %3;"
                : "=r"(fb) : "r"(bits), "r"(0x00800000u), "r"(0x3F800000u));
            float u = __uint_as_float(fb) - 1.0f;
            float m = __log2f(u) * w2;
            if (m < m1b) { m2b = m1b; m1b = m; i1b = k; }
            else         { m2b = fminf(m2b, m); }
        }
    }

    int z0 = i1a, z1 = i1b;
    if (m2a - m1a < 4e-4f + 4e-4f * m1a) {
        // Exact reference-formula rescan (verified bit-exact path).
        float best = -INF; int zi = 0;
        for (int k = 0; k < KMIX; k++) {
            uint32_t bits = tf_bits(b42_0 + (uint32_t)k, one);
            float f  = __uint_as_float(0x3F800000u | (bits >> 9)) - 1.0f;
            float uu = fmaxf(f, 1.17549435e-38f);
            float v  = -logf(-logf(uu)) + s_logit[k];
            if (v > best) { best = v; zi = k; }
        }
        z0 = zi;
    }
    if (m2b - m1b < 4e-4f + 4e-4f * m1b) {
        float best = -INF; int zi = 0;
        for (int k = 0; k < KMIX; k++) {
            uint32_t bits = tf_bits(b42_1 + (uint32_t)k, one);
            float f  = __uint_as_float(0x3F800000u | (bits >> 9)) - 1.0f;
            float uu = fmaxf(f, 1.17549435e-38f);
            float v  = -logf(-logf(uu)) + s_logit[k];
            if (v > best) { best = v; zi = k; }
        }
        z1 = zi;
    }

    // ---- warp-cooperative matvec: 8 passes, 4 lanes per sample ----
    int q = lane & 3;                        // output quarter (e = 4q..4q+3)

    #pragma unroll 1
    for (int pass = 0; pass < 8; pass++) {
        int src = (pass & 3) * 8 + (lane >> 2);   // lane holding this sample's z
        int zsel = (pass < 4) ? z0 : z1;          // uniform per pass
        int zz  = __shfl_sync(0xFFFFFFFFu, zsel, src);
        unsigned ns = warpBase + (unsigned)(pass * 8) + (unsigned)(lane >> 2);

        // x[ns]: 4 lanes per group load same addresses (L1 broadcast)
        const float4* xg = (const float4*)x + ns * 4;
        float4 xa = __ldg(xg + 0);
        float4 xb = __ldg(xg + 1);
        float4 xc = __ldg(xg + 2);
        float4 xd = __ldg(xg + 3);
        float xr[16] = { xa.x, xa.y, xa.z, xa.w,
                         xb.x, xb.y, xb.z, xb.w,
                         xc.x, xc.y, xc.z, xc.w,
                         xd.x, xd.y, xd.z, xd.w };

        const float4* L4 = (const float4*)Ls + zz * 64 + q;   // row d -> L4[d*4]
        float4 acc = __ldg((const float4*)means + zz * 4 + q);

        #pragma unroll
        for (int d = 0; d < DDIM; d++) {
            float4 lv = __ldg(L4 + d * 4);
            float xs = xr[d];
            acc.x = fmaf(xs, lv.x, acc.x);
            acc.y = fmaf(xs, lv.y, acc.y);
            acc.z = fmaf(xs, lv.z, acc.z);
            acc.w = fmaf(xs, lv.w, acc.w);
        }

        ((float4*)y)[ns * 4 + q] = acc;      // 512B contiguous per warp
    }
}

// ---------------------------------------------------------------------------
extern "C" void kernel_launch(void* const* d_in, const int* in_sizes, int n_in,
                              void* d_out, int out_size) {
    const float* x     = (const float*)d_in[0];   // (N, D)
    const float* pi    = (const float*)d_in[1];   // (K,)
    const float* means = (const float*)d_in[2];   // (K, D)
    const float* Ls    = (const float*)d_in[3];   // (K, D, D)
    float* y           = (float*)d_out;           // (N, D)

    fused_kernel<<<(NSAMP + 511) / 512, 256>>>(pi, x, means, Ls, y);
}